// round 2
// baseline (speedup 1.0000x reference)
#include <cuda_runtime.h>

// MC_Module_Batch: bilinear backward warp + weight + sum over R.
// pred [B,R,C,H,W], mv [B,R,2,H,W] (quarter-pel), weight [B,R,1,H,W] -> out [B,C,H,W]
// B=4, R=2, C=19, H=256, W=512

#define Bv 4
#define Rv 2
#define Cv 19
#define Hv 256
#define Wv 512
#define HW (Hv * Wv)

// Block = 8 rows x 32 cols tile, 256 threads, one output pixel per thread.
__global__ __launch_bounds__(256)
void mc_warp_kernel(const float* __restrict__ pred,
                    const float* __restrict__ mv,
                    const float* __restrict__ wgt,
                    float* __restrict__ out)
{
    const int tx = threadIdx.x & 31;
    const int ty = threadIdx.x >> 5;
    const int x  = blockIdx.x * 32 + tx;
    const int y  = blockIdx.y * 8  + ty;
    const int b  = blockIdx.z;
    const int pix = y * Wv + x;

    float acc[Cv];
#pragma unroll
    for (int c = 0; c < Cv; ++c) acc[c] = 0.0f;

#pragma unroll
    for (int r = 0; r < Rv; ++r) {
        const int nr = b * Rv + r;
        const float* mvp = mv + (size_t)(nr * 2) * HW;
        const float mvx = __ldg(mvp + pix) * 0.25f;
        const float mvy = __ldg(mvp + HW + pix) * 0.25f;
        const float w   = __ldg(wgt + (size_t)nr * HW + pix);

        const float gx = (float)x + mvx;
        const float gy = (float)y + mvy;
        const float x0f = floorf(gx);
        const float y0f = floorf(gy);
        const float wx1 = gx - x0f, wx0 = 1.0f - wx1;
        const float wy1 = gy - y0f, wy0 = 1.0f - wy1;

        const int x0 = (int)x0f;
        const int y0 = (int)y0f;
        const int x1 = x0 + 1;
        const int y1 = y0 + 1;

        // validity per reference ([0, dim-1] inclusive)
        const float vx0 = ((unsigned)x0 < (unsigned)Wv) ? 1.0f : 0.0f;
        const float vx1 = ((unsigned)x1 < (unsigned)Wv) ? 1.0f : 0.0f;
        const float vy0 = ((unsigned)y0 < (unsigned)Hv) ? 1.0f : 0.0f;
        const float vy1 = ((unsigned)y1 < (unsigned)Hv) ? 1.0f : 0.0f;

        // clamped sample coordinates (safe addresses)
        const int cx0 = min(max(x0, 0), Wv - 1);
        const int cx1 = min(max(x1, 0), Wv - 1);
        const int cy0 = min(max(y0, 0), Hv - 1);
        const int cy1 = min(max(y1, 0), Hv - 1);

        // per-tap weights (weight * bilinear * validity)
        const float aT = wy0 * wx0 * vy0 * vx0 * w;   // (cy0, cx0)
        const float bT = wy0 * wx1 * vy0 * vx1 * w;   // (cy0, cx1)
        const float aB = wy1 * wx0 * vy1 * vx0 * w;   // (cy1, cx0)
        const float bB = wy1 * wx1 * vy1 * vx1 * w;   // (cy1, cx1)

        // Aligned float4 window containing cx0 (and usually cx1).
        const int base = cx0 & ~3;         // in [0, 508] -> f4 load always in-bounds
        const int j    = cx0 - base;       // 0..3
        const int kB   = cx1 - base;       // 0..4 (4 == straddle into next f4)

        // Weight vectors over the 4 lanes of the f4 (built once, reused 19x)
        float wtv[4], wbv[4];
#pragma unroll
        for (int i = 0; i < 4; ++i) {
            float st = (i == j) ? aT : 0.0f;
            float sb = (i == j) ? aB : 0.0f;
            if (i == kB) { st += bT; sb += bB; }
            wtv[i] = st;
            wbv[i] = sb;
        }
        const bool straddle = (kB == 4);
        const float wxt = straddle ? bT : 0.0f;
        const float wxb = straddle ? bB : 0.0f;

        const float* pT = pred + (size_t)nr * Cv * HW + (size_t)cy0 * Wv + base;
        const float* pB = pred + (size_t)nr * Cv * HW + (size_t)cy1 * Wv + base;

#pragma unroll
        for (int c = 0; c < Cv; ++c) {
            const float4 t  = __ldg((const float4*)pT);
            const float4 bm = __ldg((const float4*)pB);
            float s;
            s = t.x * wtv[0];
            s = fmaf(t.y,  wtv[1], s);
            s = fmaf(t.z,  wtv[2], s);
            s = fmaf(t.w,  wtv[3], s);
            s = fmaf(bm.x, wbv[0], s);
            s = fmaf(bm.y, wbv[1], s);
            s = fmaf(bm.z, wbv[2], s);
            s = fmaf(bm.w, wbv[3], s);
            if (straddle) {
                s = fmaf(__ldg(pT + 4), wxt, s);
                s = fmaf(__ldg(pB + 4), wxb, s);
            }
            acc[c] += s;
            pT += HW;
            pB += HW;
        }
    }

    float* o = out + (size_t)b * Cv * HW + pix;
#pragma unroll
    for (int c = 0; c < Cv; ++c) {
        o[(size_t)c * HW] = acc[c];
    }
}

extern "C" void kernel_launch(void* const* d_in, const int* in_sizes, int n_in,
                              void* d_out, int out_size)
{
    const float* pred = (const float*)d_in[0];
    const float* mv   = (const float*)d_in[1];
    const float* wgt  = (const float*)d_in[2];
    float* out        = (float*)d_out;

    dim3 grid(Wv / 32, Hv / 8, Bv);   // 16 x 32 x 4 = 2048 blocks
    mc_warp_kernel<<<grid, 256>>>(pred, mv, wgt, out);
}